// round 15
// baseline (speedup 1.0000x reference)
#include <cuda_runtime.h>
#include <cstdint>

#define NN 1024
#define T 16
#define B 64
#define NBLK 148
#define NTHR 512
#define GSZ (NBLK * NTHR)

typedef unsigned long long ull;

// Fixed-point: value = k * 2^-24. All reference f64 math is exact (inputs are
// multiples of 2^-24, sums < 2^9 => <=33 bits), so integer DP is bit-identical.
#define SCALE 16777216.0f

// ---- scratch (device globals) ----
__device__ ull   g_dp[NN * NN];     // dp[i][j] (scaled int), row-major
__device__ ull   g_S[NN * NN];      // premasked scores (scaled int)
__device__ float g_c[NN * NN];      // premasked scores, f32 (for output)
__device__ ull   g_far[15 * B * B]; // far-split accum per tile slot
__device__ int   g_base[NN];
__device__ unsigned g_bar_arrive;
__device__ unsigned g_bar_gen;

__device__ __forceinline__ ull umaxll(ull a, ull b) { return a > b ? a : b; }

// ---- dynamic smem layout (ull); hot tiles use ODD stride 73 ----
#define STR 73
#define OFF_DI    0      /* [64][73] dI[li*73+x]   = dp[IB+li][IB+x]                */
#define OFF_DJC   4672   /* [64][73] dJc[lj*73+rp] = dp[JB+rp][JB+lj] (col-major)   */
#define OFF_DJR   9344   /* [64][73] dJr[rp*73+lj] = dp[JB+rp][JB+lj] (row-major)   */
#define OFF_CURR  14016  /* [65][73] curR[r*73+t]  = dp[IB+r][JB+t-1]; halo t=0,r=64*/
#define OFF_ST    18761  /* [64][65] S tile                                          */
#define OFF_FAR   22921  /* [64][64] far accum (gemm result + bulk folds)            */
#define OFF_CURCS 27017  /* [4][16][18] curCs[s*288+lb*18+la] = cur cell, per subtile*/
#define SMEM_ULL  28169
#define SMEM_BYTES (SMEM_ULL * 8)

// ---------------- base indices + barrier reset ----------------
__global__ void k_base(const float* __restrict__ feat) {
    int i = blockIdx.x * blockDim.x + threadIdx.x;
    if (i == 0) { g_bar_arrive = 0u; g_bar_gen = 0u; }
    if (i < NN) {
        float best = feat[(size_t)i * NN];
        int bi = 0;
        #pragma unroll
        for (int ch = 1; ch < 4; ch++) {
            float v = feat[(size_t)ch * NN * NN + (size_t)i * NN];
            if (v > best) { best = v; bi = ch; }
        }
        g_base[i] = bi;
    }
}

// ---------------- premask + zero output (coalesced via smem transpose) ------
__global__ void k_premask(const float* __restrict__ con, float* __restrict__ out) {
    __shared__ float tA[32][33], tB[32][33];
    int bx = blockIdx.x, by = blockIdx.y;
    if (bx < by) return;
    int tx = threadIdx.x, ty = threadIdx.y;   // 32x8
    int i0 = by * 32, j0 = bx * 32;
    const int pr[4] = {2, 3, 5, 7};
    #pragma unroll
    for (int rr = 0; rr < 32; rr += 8) {
        tA[ty + rr][tx] = con[(size_t)(i0 + ty + rr) * NN + j0 + tx]; // con[i][j]
        tB[ty + rr][tx] = con[(size_t)(j0 + ty + rr) * NN + i0 + tx]; // con[j][i]
    }
    __syncthreads();
    #pragma unroll
    for (int rr = 0; rr < 32; rr += 8) {
        int li = ty + rr;
        int i = i0 + li, j = j0 + tx;
        float c = 0.5f * (tA[li][tx] + tB[tx][li]);
        int dd = i - j; if (dd < 0) dd = -dd;
        int prod = pr[g_base[i]] * pr[g_base[j]];
        bool ok = (dd >= 4) && (prod == 14 || prod == 15 || prod == 35);
        float cv = ok ? c : 0.0f;
        ull kv = (ull)(cv * SCALE);   // exact: cv is a multiple of 2^-24
        g_c[i * NN + j] = cv;
        g_S[i * NN + j] = kv;
        out[i * NN + j] = 0.0f;
        g_c[j * NN + i] = cv;
        g_S[j * NN + i] = kv;
        out[j * NN + i] = 0.0f;
    }
}

// ---------------- grid-wide barrier ----------------
__device__ __forceinline__ void gridbar(unsigned& lgen) {
    __syncthreads();
    if (threadIdx.x == 0) {
        __threadfence();
        unsigned target = lgen + 1;
        if (atomicAdd(&g_bar_arrive, 1u) == NBLK - 1) {
            atomicExch(&g_bar_arrive, 0u);
            __threadfence();
            atomicAdd(&g_bar_gen, 1u);
        } else {
            while (*(volatile unsigned*)&g_bar_gen < target) __nanosleep(64);
        }
        __threadfence();
    }
    __syncthreads();
    lgen++;
}

// ---------------- diagonal tile (I,I): triangular DP in smem ----------------
__device__ void diag_tile_k(int I, ull* sm) {
    ull* tile = sm + OFF_DI;  // [64][73]
    ull* Sd   = sm + OFF_ST;  // [64][65]
    const int tid = threadIdx.x, IB = I * B;
    for (int idx = tid; idx < 64 * STR; idx += NTHR) tile[idx] = 0ULL;
    for (int idx = tid; idx < 64 * 64; idx += NTHR) {
        int r = idx >> 6, cc = idx & 63;
        Sd[r * 65 + cc] = g_S[(IB + r) * NN + IB + cc];
    }
    __syncthreads();
    const int c = tid >> 3, sub = tid & 7;
    for (int u = 1; u < 64; u++) {
        int li = c, lj = c + u;
        bool active = (lj < 64);
        ull acc = 0ULL;
        if (active) {
            for (int q = sub; q < u; q += 8) {
                int rp = li + 1 + q;
                acc = umaxll(acc, tile[li * STR + li + q] + tile[rp * STR + lj]);
            }
        }
        acc = umaxll(acc, __shfl_xor_sync(0xffffffffu, acc, 1));
        acc = umaxll(acc, __shfl_xor_sync(0xffffffffu, acc, 2));
        acc = umaxll(acc, __shfl_xor_sync(0xffffffffu, acc, 4));
        if (active && sub == 0) {
            acc = umaxll(acc, tile[(li + 1) * STR + lj - 1] + Sd[li * 65 + lj]);
            tile[li * STR + lj] = acc;
            g_dp[(IB + li) * NN + IB + lj] = acc;
        }
        __syncthreads();
    }
}

// ---------------- max-plus GEMM unit (integer) ----------------
__device__ void gemm_unit(int I, int JB, int chunk, ull* sm) {
    ull* As = sm;             // [64][33]
    ull* Bs = sm + 64 * 33;   // [32][66]
    const int tid = threadIdx.x;
    const int IB = I * B;
    const int rbase = (I + 1) * B + chunk * 32;
    __syncthreads();
    for (int idx = tid; idx < 64 * 32; idx += NTHR) {
        int li = idx >> 5, rr = idx & 31;
        As[li * 33 + rr] = g_dp[(IB + li) * NN + (rbase - 1 + rr)];
    }
    for (int idx = tid; idx < 32 * 64; idx += NTHR) {
        int rr = idx >> 6, lj = idx & 63;
        Bs[rr * 66 + lj] = g_dp[(rbase + rr) * NN + JB + lj];
    }
    __syncthreads();
    const int ty = tid >> 5, tx = tid & 31;
    ull acc[4][2];
    #pragma unroll
    for (int q = 0; q < 4; q++) { acc[q][0] = 0ULL; acc[q][1] = 0ULL; }
    #pragma unroll 4
    for (int rr = 0; rr < 32; rr++) {
        ull b0 = Bs[rr * 66 + 2 * tx];
        ull b1 = Bs[rr * 66 + 2 * tx + 1];
        #pragma unroll
        for (int q = 0; q < 4; q++) {
            ull A = As[(4 * ty + q) * 33 + rr];
            acc[q][0] = umaxll(acc[q][0], A + b0);
            acc[q][1] = umaxll(acc[q][1], A + b1);
        }
    }
    ull* far = &g_far[I * B * B];
    #pragma unroll
    for (int q = 0; q < 4; q++) {
        atomicMax(&far[(4 * ty + q) * 64 + 2 * tx], acc[q][0]);
        atomicMax(&far[(4 * ty + q) * 64 + 2 * tx + 1], acc[q][1]);
    }
}

// --------- off-diagonal tile: hierarchical subtile wavefront ----------------
// 4x4 grid of 16x16 subtiles, 7 subtile-diagonals. Per diagonal:
//   bulk: fold splits with r in finished subtiles into farS (all 512 threads)
//   wave: one warp per subtile, 31 steps, __syncwarp only.
__device__ void wave_tile(int I, int td, ull* sm) {
    ull* dI    = sm + OFF_DI;
    ull* dJc   = sm + OFF_DJC;
    ull* dJr   = sm + OFF_DJR;
    ull* curR  = sm + OFF_CURR;
    ull* St    = sm + OFF_ST;
    ull* farS  = sm + OFF_FAR;
    ull* curCs = sm + OFF_CURCS;
    const int J = I + td, tid = threadIdx.x;
    const int IB = I * B, JB = J * B;
    __syncthreads();
    for (int idx = tid; idx < 64 * 64; idx += NTHR) {
        int r = idx >> 6, cc = idx & 63;
        ull dj = g_dp[(JB + r) * NN + JB + cc];
        dI[r * STR + cc]  = g_dp[(IB + r) * NN + IB + cc];
        dJc[cc * STR + r] = dj;
        dJr[r * STR + cc] = dj;
        St[r * 65 + cc]   = g_S[(IB + r) * NN + JB + cc];
        farS[idx]         = g_far[I * B * B + idx];
    }
    for (int t = tid; t < 64; t += NTHR)
        curR[t * STR + 0] = g_dp[(IB + t) * NN + (JB - 1)];
    for (int t = tid; t < 65; t += NTHR)
        curR[64 * STR + t] = g_dp[(IB + 64) * NN + (JB - 1 + t)];
    __syncthreads();

    const int w = tid >> 5, lane = tid & 31;
    const int c = lane >> 1, sub = lane & 1;

    for (int sd = 0; sd < 7; sd++) {
        const int blo = sd > 3 ? sd - 3 : 0;
        const int bhi = sd < 3 ? sd : 3;
        const int nsub = bhi - blo + 1;

        // ---- bulk: r in finished subtiles -> fold into farS ----
        {
            const int cells = nsub << 8;
            for (int cell = tid; cell < cells; cell += NTHR) {
                int s = cell >> 8, cid = cell & 255;
                int la = cid >> 4, lb = cid & 15;
                int b = blo + s, a = 3 - sd + b;
                int li = (a << 4) + la, lj = (b << 4) + lb;
                ull acc = farS[li * 64 + lj];
                for (int rp = (a << 4) + 16; rp < 64; rp++)     // rows below subtile
                    acc = umaxll(acc, dI[li * STR + rp - 1] + curR[rp * STR + lj + 1]);
                int rmax = b << 4;
                for (int rpp = 0; rpp <= rmax; rpp++)           // cols left of subtile (incl halo)
                    acc = umaxll(acc, curR[li * STR + rpp] + dJr[rpp * STR + lj]);
                farS[li * 64 + lj] = acc;
            }
        }
        __syncthreads();

        // ---- wave: warp-private 16x16 wavefront ----
        if (w < nsub) {
            const int b = blo + w, a = 3 - sd + b;
            const int sbase = w * 288;
            for (int ul = 0; ul < 31; ul++) {
                int lb0 = ul > 15 ? ul - 15 : 0;
                int cnt = (ul < 15 ? ul : 15) - lb0 + 1;
                bool active = (c < cnt);
                ull acc = 0ULL;
                int li = 0, lj = 0, la = 0, lb = 0;
                if (active) {
                    lb = lb0 + c;
                    la = 15 - (ul - lb);
                    li = (a << 4) + la; lj = (b << 4) + lb;
                    int ka = 15 - la;
                    for (int q = sub; q < ka; q += 2)            // r inside subtile (below)
                        acc = umaxll(acc, dI[li * STR + li + q] + curCs[sbase + lb * 18 + la + 1 + q]);
                    int base = (b << 4) + 1;
                    for (int m = sub; m < lb; m += 2)            // r inside subtile (left)
                        acc = umaxll(acc, curR[li * STR + base + m] + dJc[lj * STR + base + m]);
                }
                acc = umaxll(acc, __shfl_xor_sync(0xffffffffu, acc, 1));
                if (active && sub == 0) {
                    acc = umaxll(acc, farS[li * 64 + lj]);
                    acc = umaxll(acc, curR[(li + 1) * STR + lj] + St[li * 65 + lj]);
                    curR[li * STR + lj + 1] = acc;
                    curCs[sbase + lb * 18 + la] = acc;
                }
                __syncwarp();
            }
        }
        __syncthreads();
    }

    // write back + reset far slot
    for (int idx = tid; idx < 64 * 64; idx += NTHR) {
        int r = idx >> 6, cc = idx & 63;
        g_dp[(IB + r) * NN + JB + cc] = curR[r * STR + cc + 1];
        g_far[I * B * B + idx] = 0ULL;
    }
}

// ---------------- persistent blocked DP ----------------
__global__ void __launch_bounds__(NTHR, 1) k_dp() {
    extern __shared__ ull sm[];
    const int gtid = blockIdx.x * NTHR + threadIdx.x;
    unsigned lgen = 0;

    for (int idx = gtid; idx < NN * NN; idx += GSZ) g_dp[idx] = 0ULL;
    for (int idx = gtid; idx < 15 * B * B; idx += GSZ) g_far[idx] = 0ULL;
    gridbar(lgen);

    if (blockIdx.x < T) diag_tile_k(blockIdx.x, sm);
    gridbar(lgen);

    for (int td = 1; td < T; td++) {
        const int nt = T - td;
        if (td >= 2) {
            const int nchunks = (td - 1) * 2;
            const int units = nt * nchunks;
            for (int u = blockIdx.x; u < units; u += NBLK) {
                int I = u % nt;
                int chunk = u / nt;
                gemm_unit(I, (I + td) * B, chunk, sm);
            }
        }
        gridbar(lgen);
        if (blockIdx.x < nt) wave_tile(blockIdx.x, td, sm);
        gridbar(lgen);
    }
}

// ------------- warp-parallel traceback (1 CTA, 32 warps, integer) ----------
__global__ void __launch_bounds__(1024, 1) k_traceback(float* __restrict__ out) {
    const int tid = threadIdx.x;
    const int lane = tid & 31;
    __shared__ int2 stk[4096];
    __shared__ int top, pending, lock;
    if (tid == 0) { stk[0] = make_int2(0, NN - 1); top = 1; pending = 1; lock = 0; }
    __syncthreads();

    volatile int* vtop = &top;
    volatile int* vpend = &pending;
    int ci = 0, cj = 0;
    bool have = false;
    long long guard = 0;

    while (true) {
        if (++guard > 80000000LL) break;
        if (!have) {
            int got = 0, ex = 0, ei = 0, ej = 0;
            if (lane == 0) {
                if (atomicCAS(&lock, 0, 1) == 0) {
                    __threadfence_block();
                    int t = *vtop;
                    if (t > 0) { int2 e = stk[t - 1]; *vtop = t - 1; ei = e.x; ej = e.y; got = 1; }
                    __threadfence_block();
                    atomicExch(&lock, 0);
                }
                if (!got && *vpend == 0) ex = 1;
            }
            got = __shfl_sync(0xffffffffu, got, 0);
            ex  = __shfl_sync(0xffffffffu, ex, 0);
            if (got) {
                ci = __shfl_sync(0xffffffffu, ei, 0);
                cj = __shfl_sync(0xffffffffu, ej, 0);
                have = true;
            } else if (ex) {
                break;
            } else {
                __nanosleep(64);
                continue;
            }
        }

        int i = ci, j = cj;
        if (j <= i) { have = false; if (lane == 0) atomicSub(&pending, 1); __syncwarp(); continue; }
        ull v = g_dp[i * NN + j];
        if (v == 0ULL) { have = false; if (lane == 0) atomicSub(&pending, 1); __syncwarp(); continue; }
        ull up    = g_dp[(i + 1) * NN + j];
        ull inner = g_dp[(i + 1) * NN + (j - 1)];
        ull s     = g_S[i * NN + j];
        if (up >= v) { ci = i + 1; continue; }
        if (s != 0ULL && inner + s >= v) {
            if (lane == 0) {
                out[i * NN + j] = g_c[i * NN + j];
                out[j * NN + i] = g_c[j * NN + i];
            }
            ci = i + 1; cj = j - 1;
            continue;
        }
        ull bestv = 0ULL;
        int bestk = NN + 1;
        for (int k = i + lane; k < j; k += 32) {
            ull val = g_dp[i * NN + k] + g_dp[(k + 1) * NN + j];
            if (val > bestv) { bestv = val; bestk = k; }
        }
        #pragma unroll
        for (int off = 16; off > 0; off >>= 1) {
            ull ov = __shfl_down_sync(0xffffffffu, bestv, off);
            int oi = __shfl_down_sync(0xffffffffu, bestk, off);
            if (ov > bestv || (ov == bestv && oi < bestk)) { bestv = ov; bestk = oi; }
        }
        int k = __shfl_sync(0xffffffffu, bestk, 0);
        if (lane == 0) {
            atomicAdd(&pending, 1);
            while (atomicCAS(&lock, 0, 1) != 0) __nanosleep(32);
            __threadfence_block();
            int t = *vtop;
            stk[t] = make_int2(i, k);
            *vtop = t + 1;
            __threadfence_block();
            atomicExch(&lock, 0);
        }
        __syncwarp();
        ci = k + 1;
    }
}

// ---------------- launch (4 graph nodes) ----------------
extern "C" void kernel_launch(void* const* d_in, const int* in_sizes, int n_in,
                              void* d_out, int out_size) {
    const float* con  = (const float*)d_in[0];
    const float* feat = (const float*)d_in[1];
    float* out = (float*)d_out;

    static int smem_set = 0;
    if (!smem_set) {
        cudaFuncSetAttribute(k_dp, cudaFuncAttributeMaxDynamicSharedMemorySize, SMEM_BYTES);
        smem_set = 1;
    }

    k_base<<<(NN + 255) / 256, 256>>>(feat);
    k_premask<<<dim3(32, 32), dim3(32, 8)>>>(con, out);
    k_dp<<<NBLK, NTHR, SMEM_BYTES>>>();
    k_traceback<<<1, 1024>>>(out);
}

// round 17
// speedup vs baseline: 1.5134x; 1.5134x over previous
#include <cuda_runtime.h>
#include <cstdint>

#define NN 1024
#define T 16
#define B 64
#define NBLK 148
#define NTHR 512
#define GSZ (NBLK * NTHR)

typedef unsigned long long ull;

// Fixed-point: value = k * 2^-24. All reference f64 math is exact (inputs are
// multiples of 2^-24, sums < 2^9 => <=33 bits), so integer DP is bit-identical.
#define SCALE 16777216.0f

// ---- scratch (device globals) ----
__device__ ull   g_dp[NN * NN];     // dp[i][j] (scaled int), row-major
__device__ ull   g_S[NN * NN];      // premasked scores (scaled int)
__device__ float g_c[NN * NN];      // premasked scores, f32 (for output)
__device__ ull   g_far[15 * B * B]; // far-split accum per tile slot
__device__ int   g_base[NN];
__device__ unsigned g_bar_arrive;
__device__ unsigned g_bar_gen;

__device__ __forceinline__ ull umaxll(ull a, ull b) { return a > b ? a : b; }

// ---- dynamic smem layout (ull); hot arrays padded to stride 72 ----
#define STR 72
#define OFF_DI   0        /* [64][72] dI[li][x]   = dp[IB+li][IB+x]                 */
#define OFF_DJ   4608     /* [64][72] dJc[lj][rp] = dp[JB+rp][JB+lj] (col-major)    */
#define OFF_CURC 9216     /* [64][72] curC[lj][rp]= cur(rp,lj)       (col-major)    */
#define OFF_CURR 13824    /* [65][72] curR[r][t]  = dp[IB+r][JB+t-1] (halo t=0,r=64)*/
#define OFF_ST   18504    /* [64][65] S tile                                        */
#define OFF_FAR  22664    /* [64][64] far accum                                     */
#define SMEM_ULL 26760
#define SMEM_BYTES (SMEM_ULL * 8)

// ---------------- base indices + barrier reset ----------------
__global__ void k_base(const float* __restrict__ feat) {
    int i = blockIdx.x * blockDim.x + threadIdx.x;
    if (i == 0) { g_bar_arrive = 0u; g_bar_gen = 0u; }
    if (i < NN) {
        float best = feat[(size_t)i * NN];
        int bi = 0;
        #pragma unroll
        for (int ch = 1; ch < 4; ch++) {
            float v = feat[(size_t)ch * NN * NN + (size_t)i * NN];
            if (v > best) { best = v; bi = ch; }
        }
        g_base[i] = bi;
    }
}

// ---------------- premask + zero output (coalesced via smem transpose) ------
__global__ void k_premask(const float* __restrict__ con, float* __restrict__ out) {
    __shared__ float tA[32][33], tB[32][33];
    int bx = blockIdx.x, by = blockIdx.y;
    if (bx < by) return;
    int tx = threadIdx.x, ty = threadIdx.y;   // 32x8
    int i0 = by * 32, j0 = bx * 32;
    const int pr[4] = {2, 3, 5, 7};
    #pragma unroll
    for (int rr = 0; rr < 32; rr += 8) {
        tA[ty + rr][tx] = con[(size_t)(i0 + ty + rr) * NN + j0 + tx]; // con[i][j]
        tB[ty + rr][tx] = con[(size_t)(j0 + ty + rr) * NN + i0 + tx]; // con[j][i]
    }
    __syncthreads();
    #pragma unroll
    for (int rr = 0; rr < 32; rr += 8) {
        int li = ty + rr;
        int i = i0 + li, j = j0 + tx;
        float c = 0.5f * (tA[li][tx] + tB[tx][li]);
        int dd = i - j; if (dd < 0) dd = -dd;
        int prod = pr[g_base[i]] * pr[g_base[j]];
        bool ok = (dd >= 4) && (prod == 14 || prod == 15 || prod == 35);
        float cv = ok ? c : 0.0f;
        ull kv = (ull)(cv * SCALE);   // exact: cv is a multiple of 2^-24
        g_c[i * NN + j] = cv;
        g_S[i * NN + j] = kv;
        out[i * NN + j] = 0.0f;
        g_c[j * NN + i] = cv;
        g_S[j * NN + i] = kv;
        out[j * NN + i] = 0.0f;
    }
}

// ---------------- grid-wide barrier ----------------
__device__ __forceinline__ void gridbar(unsigned& lgen) {
    __syncthreads();
    if (threadIdx.x == 0) {
        __threadfence();
        unsigned target = lgen + 1;
        if (atomicAdd(&g_bar_arrive, 1u) == NBLK - 1) {
            atomicExch(&g_bar_arrive, 0u);
            __threadfence();
            atomicAdd(&g_bar_gen, 1u);
        } else {
            while (*(volatile unsigned*)&g_bar_gen < target) __nanosleep(64);
        }
        __threadfence();
    }
    __syncthreads();
    lgen++;
}

// ---------------- diagonal tile (I,I): triangular DP in smem ----------------
__device__ void diag_tile_k(int I, ull* sm) {
    ull* tile = sm + OFF_DI;  // [64][72]
    ull* Sd   = sm + OFF_ST;  // [64][65]
    const int tid = threadIdx.x, IB = I * B;
    for (int idx = tid; idx < 64 * STR; idx += NTHR) tile[idx] = 0ULL;
    for (int idx = tid; idx < 64 * 64; idx += NTHR) {
        int r = idx >> 6, cc = idx & 63;
        Sd[r * 65 + cc] = g_S[(IB + r) * NN + IB + cc];
    }
    __syncthreads();
    const int c = tid >> 3, sub = tid & 7;
    for (int u = 1; u < 64; u++) {
        int li = c, lj = c + u;
        bool active = (lj < 64);
        ull acc = 0ULL;
        if (active) {
            for (int q = sub; q < u; q += 8) {
                int rp = li + 1 + q;
                acc = umaxll(acc, tile[li * STR + li + q] + tile[rp * STR + lj]);
            }
        }
        acc = umaxll(acc, __shfl_xor_sync(0xffffffffu, acc, 1));
        acc = umaxll(acc, __shfl_xor_sync(0xffffffffu, acc, 2));
        acc = umaxll(acc, __shfl_xor_sync(0xffffffffu, acc, 4));
        if (active && sub == 0) {
            acc = umaxll(acc, tile[(li + 1) * STR + lj - 1] + Sd[li * 65 + lj]);
            tile[li * STR + lj] = acc;
            g_dp[(IB + li) * NN + IB + lj] = acc;
        }
        __syncthreads();
    }
}

// ---------------- max-plus GEMM unit (integer) ----------------
__device__ void gemm_unit(int I, int JB, int chunk, ull* sm) {
    ull* As = sm;             // [64][33]
    ull* Bs = sm + 64 * 33;   // [32][66]
    const int tid = threadIdx.x;
    const int IB = I * B;
    const int rbase = (I + 1) * B + chunk * 32;
    __syncthreads();
    for (int idx = tid; idx < 64 * 32; idx += NTHR) {
        int li = idx >> 5, rr = idx & 31;
        As[li * 33 + rr] = g_dp[(IB + li) * NN + (rbase - 1 + rr)];
    }
    for (int idx = tid; idx < 32 * 64; idx += NTHR) {
        int rr = idx >> 6, lj = idx & 63;
        Bs[rr * 66 + lj] = g_dp[(rbase + rr) * NN + JB + lj];
    }
    __syncthreads();
    const int ty = tid >> 5, tx = tid & 31;
    ull acc[4][2];
    #pragma unroll
    for (int q = 0; q < 4; q++) { acc[q][0] = 0ULL; acc[q][1] = 0ULL; }
    #pragma unroll 4
    for (int rr = 0; rr < 32; rr++) {
        ull b0 = Bs[rr * 66 + 2 * tx];
        ull b1 = Bs[rr * 66 + 2 * tx + 1];
        #pragma unroll
        for (int q = 0; q < 4; q++) {
            ull A = As[(4 * ty + q) * 33 + rr];
            acc[q][0] = umaxll(acc[q][0], A + b0);
            acc[q][1] = umaxll(acc[q][1], A + b1);
        }
    }
    ull* far = &g_far[I * B * B];
    #pragma unroll
    for (int q = 0; q < 4; q++) {
        atomicMax(&far[(4 * ty + q) * 64 + 2 * tx], acc[q][0]);
        atomicMax(&far[(4 * ty + q) * 64 + 2 * tx + 1], acc[q][1]);
    }
}

// ------- off-diagonal tile wavefront: R12 structure, de-chained step --------
__device__ void wave_tile(int I, int td, ull* sm) {
    ull* dI   = sm + OFF_DI;    // [64][72]
    ull* dJc  = sm + OFF_DJ;    // [64][72] col-major (J,J)
    ull* curC = sm + OFF_CURC;  // [64][72] col-major cur
    ull* curR = sm + OFF_CURR;  // [65][72] row-major cur + halos
    ull* St   = sm + OFF_ST;    // [64][65]
    ull* farS = sm + OFF_FAR;   // [64][64]
    const int J = I + td, tid = threadIdx.x;
    const int IB = I * B, JB = J * B;
    __syncthreads();
    for (int idx = tid; idx < 64 * 64; idx += NTHR) {
        int r = idx >> 6, cc = idx & 63;
        dI[r * STR + cc]  = g_dp[(IB + r) * NN + IB + cc];
        dJc[cc * STR + r] = g_dp[(JB + r) * NN + JB + cc];
        St[r * 65 + cc]   = g_S[(IB + r) * NN + JB + cc];
        farS[idx]         = g_far[I * B * B + idx];
    }
    for (int t = tid; t < 64; t += NTHR)
        curR[t * STR + 0] = g_dp[(IB + t) * NN + (JB - 1)];
    for (int t = tid; t < 65; t += NTHR)
        curR[64 * STR + t] = g_dp[(IB + 64) * NN + (JB - 1 + t)];
    __syncthreads();

    const int c = tid >> 3, sub = tid & 7;
    for (int u = 0; u < 2 * B - 1; u++) {
        int lo = u > 63 ? u - 63 : 0;
        int hi = u < 63 ? u : 63;
        int lj = lo + c;
        int li = 63 - u + lj;
        bool active = (lj <= hi);
        ull acc0 = 0ULL, acc1 = 0ULL;   // two independent chains
        if (active) {
            int lenA = 63 - li;
            if (sub == 0) {
                // far + pair folded in early (their LDS issues at step start)
                acc0 = farS[li * 64 + lj];
                acc1 = curR[(li + 1) * STR + lj] + St[li * 65 + lj];
            }
            // split r in tile I: q ≡ sub (mod 8), 2-way unrolled
            {
                const ull* pa = dI + li * STR + li;          // [q]
                const ull* pc = curC + lj * STR + li + 1;    // [q]
                int q = sub;
                for (; q + 8 < lenA; q += 16) {
                    acc0 = umaxll(acc0, pa[q] + pc[q]);
                    acc1 = umaxll(acc1, pa[q + 8] + pc[q + 8]);
                }
                if (q < lenA) acc0 = umaxll(acc0, pa[q] + pc[q]);
            }
            // split r in tile J: rpp ≡ (sub-lenA) (mod 8), 2-way unrolled
            {
                const ull* pr = curR + li * STR;             // [rpp]
                const ull* pj = dJc + lj * STR;              // [rpp]
                int rpp = (sub - lenA) & 7;
                for (; rpp + 8 <= lj; rpp += 16) {
                    acc1 = umaxll(acc1, pr[rpp] + pj[rpp]);
                    acc0 = umaxll(acc0, pr[rpp + 8] + pj[rpp + 8]);
                }
                if (rpp <= lj) acc1 = umaxll(acc1, pr[rpp] + pj[rpp]);
            }
        }
        ull acc = umaxll(acc0, acc1);
        acc = umaxll(acc, __shfl_xor_sync(0xffffffffu, acc, 1));
        acc = umaxll(acc, __shfl_xor_sync(0xffffffffu, acc, 2));
        acc = umaxll(acc, __shfl_xor_sync(0xffffffffu, acc, 4));
        if (active && sub == 0) {
            curR[li * STR + lj + 1] = acc;   // writer tail: 2 STS only
            curC[lj * STR + li] = acc;
        }
        __syncthreads();
    }

    // bulk coalesced writeback + far slot reset (no per-step STG)
    for (int idx = tid; idx < 64 * 64; idx += NTHR) {
        int r = idx >> 6, cc = idx & 63;
        g_dp[(IB + r) * NN + JB + cc] = curR[r * STR + cc + 1];
        g_far[I * B * B + idx] = 0ULL;
    }
}

// ---------------- persistent blocked DP ----------------
__global__ void __launch_bounds__(NTHR, 1) k_dp() {
    extern __shared__ ull sm[];
    const int gtid = blockIdx.x * NTHR + threadIdx.x;
    unsigned lgen = 0;

    for (int idx = gtid; idx < NN * NN; idx += GSZ) g_dp[idx] = 0ULL;
    for (int idx = gtid; idx < 15 * B * B; idx += GSZ) g_far[idx] = 0ULL;
    gridbar(lgen);

    if (blockIdx.x < T) diag_tile_k(blockIdx.x, sm);
    gridbar(lgen);

    for (int td = 1; td < T; td++) {
        const int nt = T - td;
        if (td >= 2) {
            const int nchunks = (td - 1) * 2;
            const int units = nt * nchunks;
            for (int u = blockIdx.x; u < units; u += NBLK) {
                int I = u % nt;
                int chunk = u / nt;
                gemm_unit(I, (I + td) * B, chunk, sm);
            }
        }
        gridbar(lgen);
        if (blockIdx.x < nt) wave_tile(blockIdx.x, td, sm);
        gridbar(lgen);
    }
}

// ------------- warp-parallel traceback (1 CTA, 32 warps, integer) ----------
__global__ void __launch_bounds__(1024, 1) k_traceback(float* __restrict__ out) {
    const int tid = threadIdx.x;
    const int lane = tid & 31;
    __shared__ int2 stk[4096];
    __shared__ int top, pending, lock;
    if (tid == 0) { stk[0] = make_int2(0, NN - 1); top = 1; pending = 1; lock = 0; }
    __syncthreads();

    volatile int* vtop = &top;
    volatile int* vpend = &pending;
    int ci = 0, cj = 0;
    bool have = false;
    long long guard = 0;

    while (true) {
        if (++guard > 80000000LL) break;
        if (!have) {
            int got = 0, ex = 0, ei = 0, ej = 0;
            if (lane == 0) {
                if (atomicCAS(&lock, 0, 1) == 0) {
                    __threadfence_block();
                    int t = *vtop;
                    if (t > 0) { int2 e = stk[t - 1]; *vtop = t - 1; ei = e.x; ej = e.y; got = 1; }
                    __threadfence_block();
                    atomicExch(&lock, 0);
                }
                if (!got && *vpend == 0) ex = 1;
            }
            got = __shfl_sync(0xffffffffu, got, 0);
            ex  = __shfl_sync(0xffffffffu, ex, 0);
            if (got) {
                ci = __shfl_sync(0xffffffffu, ei, 0);
                cj = __shfl_sync(0xffffffffu, ej, 0);
                have = true;
            } else if (ex) {
                break;
            } else {
                __nanosleep(64);
                continue;
            }
        }

        int i = ci, j = cj;
        if (j <= i) { have = false; if (lane == 0) atomicSub(&pending, 1); __syncwarp(); continue; }
        ull v = g_dp[i * NN + j];
        if (v == 0ULL) { have = false; if (lane == 0) atomicSub(&pending, 1); __syncwarp(); continue; }
        ull up    = g_dp[(i + 1) * NN + j];
        ull inner = g_dp[(i + 1) * NN + (j - 1)];
        ull s     = g_S[i * NN + j];
        if (up >= v) { ci = i + 1; continue; }
        if (s != 0ULL && inner + s >= v) {
            if (lane == 0) {
                out[i * NN + j] = g_c[i * NN + j];
                out[j * NN + i] = g_c[j * NN + i];
            }
            ci = i + 1; cj = j - 1;
            continue;
        }
        ull bestv = 0ULL;
        int bestk = NN + 1;
        for (int k = i + lane; k < j; k += 32) {
            ull val = g_dp[i * NN + k] + g_dp[(k + 1) * NN + j];
            if (val > bestv) { bestv = val; bestk = k; }
        }
        #pragma unroll
        for (int off = 16; off > 0; off >>= 1) {
            ull ov = __shfl_down_sync(0xffffffffu, bestv, off);
            int oi = __shfl_down_sync(0xffffffffu, bestk, off);
            if (ov > bestv || (ov == bestv && oi < bestk)) { bestv = ov; bestk = oi; }
        }
        int k = __shfl_sync(0xffffffffu, bestk, 0);
        if (lane == 0) {
            atomicAdd(&pending, 1);
            while (atomicCAS(&lock, 0, 1) != 0) __nanosleep(32);
            __threadfence_block();
            int t = *vtop;
            stk[t] = make_int2(i, k);
            *vtop = t + 1;
            __threadfence_block();
            atomicExch(&lock, 0);
        }
        __syncwarp();
        ci = k + 1;
    }
}

// ---------------- launch (4 graph nodes) ----------------
extern "C" void kernel_launch(void* const* d_in, const int* in_sizes, int n_in,
                              void* d_out, int out_size) {
    const float* con  = (const float*)d_in[0];
    const float* feat = (const float*)d_in[1];
    float* out = (float*)d_out;

    static int smem_set = 0;
    if (!smem_set) {
        cudaFuncSetAttribute(k_dp, cudaFuncAttributeMaxDynamicSharedMemorySize, SMEM_BYTES);
        smem_set = 1;
    }

    k_base<<<(NN + 255) / 256, 256>>>(feat);
    k_premask<<<dim3(32, 32), dim3(32, 8)>>>(con, out);
    k_dp<<<NBLK, NTHR, SMEM_BYTES>>>();
    k_traceback<<<1, 1024>>>(out);
}